// round 1
// baseline (speedup 1.0000x reference)
#include <cuda_runtime.h>
#include <cuda_bf16.h>
#include <cstddef>

// Problem constants
#define BATCH 4
#define SEQ   1024
#define DMODEL 512
#define HEADS 8
#define DEPTH 64
#define DFF   2048
#define NLAYERS 4
#define ROWS  (BATCH*SEQ)          // 4096
#define BH    (BATCH*HEADS)        // 32
#define LSIZE ((size_t)BH*SEQ*SEQ) // 33554432
#define XSIZE (ROWS*DMODEL)        // 2097152

// -------- scratch (device globals; no allocations) --------
__device__ float g_q[XSIZE];
__device__ float g_k[XSIZE];
__device__ float g_v[XSIZE];
__device__ float g_ao[XSIZE];
__device__ float g_res[XSIZE];
__device__ float g_o1[XSIZE];
__device__ float g_x[XSIZE];
__device__ float g_h[ROWS*DFF];
__device__ float g_L[LSIZE];
__device__ float g_pm[BH*64];
__device__ float g_ps[BH*64];
__device__ float g_M[BH];
__device__ float g_Z[BH];
__device__ float g_rc;

// -------- fast exp (FMA pipe, avoids MUFU throughput wall) --------
__device__ __forceinline__ float fexp(float x) {
    float t = x * 1.44269504089f;          // log2(e)
    t = fmaxf(t, -126.0f);
    float fi = floorf(t);
    float f  = t - fi;
    // degree-6 Taylor of 2^f on [0,1): max rel err ~2e-5
    float p = 1.54035304e-4f;
    p = fmaf(p, f, 1.33335581e-3f);
    p = fmaf(p, f, 9.61812911e-3f);
    p = fmaf(p, f, 5.55041087e-2f);
    p = fmaf(p, f, 2.40226507e-1f);
    p = fmaf(p, f, 6.93147181e-1f);
    p = fmaf(p, f, 1.0f);
    int ei = (int)fi;
    return __int_as_float((ei + 127) << 23) * p;
}

// -------- row count: count_nonzero(protok[0,:]) --------
__global__ void rc_k(const int* __restrict__ pk) {
    __shared__ int red[1024];
    int tid = threadIdx.x;
    red[tid] = (pk[tid] != 0) ? 1 : 0;
    __syncthreads();
    for (int s = 512; s > 0; s >>= 1) {
        if (tid < s) red[tid] += red[tid + s];
        __syncthreads();
    }
    if (tid == 0) g_rc = (float)red[0];
}

// -------- generic GEMM: C[M,N] = A[M,K] @ B[K,N] + bias (+res) (opt relu) --------
// BM=128, BN=64, BK=16, 256 threads, 8x4 microtile
template<bool RELU, bool RES>
__global__ void __launch_bounds__(256) gemm_k(
    const float* __restrict__ A, const float* __restrict__ Bw,
    const float* __restrict__ bias, const float* __restrict__ Rs,
    float* __restrict__ C, int M, int N, int K)
{
    __shared__ float As[16][129];
    __shared__ float Bs[16][65];
    const int m0 = blockIdx.y << 7, n0 = blockIdx.x << 6;
    const int tid = threadIdx.x;
    const int tx = tid & 15, ty = tid >> 4;
    const int ar = tid >> 2, ac4 = tid & 3;     // A: rows ar, ar+64; k-chunk ac4
    const int br = tid >> 4, bc4 = tid & 15;    // B: row br; col chunk bc4
    float acc[8][4] = {};
    for (int k0 = 0; k0 < K; k0 += 16) {
        float4 a0 = *(const float4*)(A + (size_t)(m0 + ar) * K + k0 + ac4 * 4);
        float4 a1 = *(const float4*)(A + (size_t)(m0 + ar + 64) * K + k0 + ac4 * 4);
        float4 b0 = *(const float4*)(Bw + (size_t)(k0 + br) * N + n0 + bc4 * 4);
        __syncthreads();
        As[ac4*4+0][ar] = a0.x; As[ac4*4+1][ar] = a0.y;
        As[ac4*4+2][ar] = a0.z; As[ac4*4+3][ar] = a0.w;
        As[ac4*4+0][ar+64] = a1.x; As[ac4*4+1][ar+64] = a1.y;
        As[ac4*4+2][ar+64] = a1.z; As[ac4*4+3][ar+64] = a1.w;
        Bs[br][bc4*4+0] = b0.x; Bs[br][bc4*4+1] = b0.y;
        Bs[br][bc4*4+2] = b0.z; Bs[br][bc4*4+3] = b0.w;
        __syncthreads();
        #pragma unroll
        for (int k = 0; k < 16; k++) {
            float a[8], b[4];
            #pragma unroll
            for (int i = 0; i < 8; i++) a[i] = As[k][ty*8 + i];
            #pragma unroll
            for (int j = 0; j < 4; j++) b[j] = Bs[k][tx*4 + j];
            #pragma unroll
            for (int i = 0; i < 8; i++)
                #pragma unroll
                for (int j = 0; j < 4; j++)
                    acc[i][j] = fmaf(a[i], b[j], acc[i][j]);
        }
    }
    #pragma unroll
    for (int i = 0; i < 8; i++) {
        int m = m0 + ty*8 + i;
        #pragma unroll
        for (int j = 0; j < 4; j++) {
            int n = n0 + tx*4 + j;
            float v = acc[i][j] + bias[n];
            if (RES) v += Rs[(size_t)m * N + n];
            if (RELU) v = fmaxf(v, 0.0f);
            C[(size_t)m * N + n] = v;
        }
    }
}

// -------- QK^T + mask + scale -> logits  (per bh, 64x64 tiles, K=64) --------
__global__ void __launch_bounds__(256) qk_k(
    const float* __restrict__ Q, const float* __restrict__ Km,
    const float* __restrict__ mask, float* __restrict__ L)
{
    __shared__ float Qs[64][65];   // [i][d]
    __shared__ float Kt[64][65];   // [d][j]
    const int bh = blockIdx.z, b = bh >> 3, h = bh & 7;
    const int i0 = blockIdx.y << 6, j0 = blockIdx.x << 6;
    const int tid = threadIdx.x;
    const int r = tid >> 4, c4 = tid & 15;
    #pragma unroll
    for (int rr = 0; rr < 4; rr++) {
        int row = r + rr * 16;
        float4 q4 = *(const float4*)(Q + (size_t)(b*SEQ + i0 + row) * DMODEL + h*DEPTH + c4*4);
        float4 k4 = *(const float4*)(Km + (size_t)(b*SEQ + j0 + row) * DMODEL + h*DEPTH + c4*4);
        Qs[row][c4*4+0] = q4.x; Qs[row][c4*4+1] = q4.y;
        Qs[row][c4*4+2] = q4.z; Qs[row][c4*4+3] = q4.w;
        Kt[c4*4+0][row] = k4.x; Kt[c4*4+1][row] = k4.y;
        Kt[c4*4+2][row] = k4.z; Kt[c4*4+3][row] = k4.w;
    }
    __syncthreads();
    const int ty = tid >> 4, tx = tid & 15;
    float acc[4][4] = {};
    #pragma unroll
    for (int d = 0; d < 64; d++) {
        float a[4], bb[4];
        #pragma unroll
        for (int i = 0; i < 4; i++) a[i] = Qs[ty*4 + i][d];
        #pragma unroll
        for (int j = 0; j < 4; j++) bb[j] = Kt[d][tx*4 + j];
        #pragma unroll
        for (int i = 0; i < 4; i++)
            #pragma unroll
            for (int j = 0; j < 4; j++)
                acc[i][j] = fmaf(a[i], bb[j], acc[i][j]);
    }
    #pragma unroll
    for (int i = 0; i < 4; i++) {
        int gi = i0 + ty*4 + i;
        #pragma unroll
        for (int j = 0; j < 4; j++) {
            int gj = j0 + tx*4 + j;
            float mv = mask[(size_t)(b*SEQ + gi) * SEQ + gj];
            L[((size_t)bh << 20) + (size_t)gi * SEQ + gj] =
                (acc[i][j] - 1e9f * mv) * 0.125f;
        }
    }
}

// -------- softmax stats: pass 1 max --------
__global__ void max_k(const float* __restrict__ L) {
    const int bh = blockIdx.y, blk = blockIdx.x, tid = threadIdx.x;
    const float4* p = (const float4*)(L + ((size_t)bh << 20) + (size_t)blk * 16384);
    float m = -3.4e38f;
    #pragma unroll
    for (int it = 0; it < 16; it++) {
        float4 v = p[tid + it * 256];
        m = fmaxf(m, fmaxf(fmaxf(v.x, v.y), fmaxf(v.z, v.w)));
    }
    __shared__ float red[256];
    red[tid] = m; __syncthreads();
    for (int s = 128; s > 0; s >>= 1) {
        if (tid < s) red[tid] = fmaxf(red[tid], red[tid + s]);
        __syncthreads();
    }
    if (tid == 0) g_pm[bh * 64 + blk] = red[0];
}

__global__ void cmax_k() {
    const int bh = blockIdx.x, tid = threadIdx.x;
    __shared__ float red[64];
    red[tid] = g_pm[bh * 64 + tid]; __syncthreads();
    for (int s = 32; s > 0; s >>= 1) {
        if (tid < s) red[tid] = fmaxf(red[tid], red[tid + s]);
        __syncthreads();
    }
    if (tid == 0) g_M[bh] = red[0];
}

// -------- pass 2: P = exp(L - M) (overwrite), accumulate sum --------
__global__ void sexp_k(float* __restrict__ L) {
    const int bh = blockIdx.y, blk = blockIdx.x, tid = threadIdx.x;
    const float M = g_M[bh];
    float4* p = (float4*)(L + ((size_t)bh << 20) + (size_t)blk * 16384);
    float s = 0.0f;
    #pragma unroll
    for (int it = 0; it < 16; it++) {
        float4 v = p[tid + it * 256];
        v.x = fexp(v.x - M); v.y = fexp(v.y - M);
        v.z = fexp(v.z - M); v.w = fexp(v.w - M);
        p[tid + it * 256] = v;
        s += (v.x + v.y) + (v.z + v.w);
    }
    __shared__ float red[256];
    red[tid] = s; __syncthreads();
    for (int st = 128; st > 0; st >>= 1) {
        if (tid < st) red[tid] += red[tid + st];
        __syncthreads();
    }
    if (tid == 0) g_ps[bh * 64 + blk] = red[0];
}

__global__ void csum_k() {
    const int bh = blockIdx.x, tid = threadIdx.x;
    __shared__ float red[64];
    red[tid] = g_ps[bh * 64 + tid]; __syncthreads();
    for (int s = 32; s > 0; s >>= 1) {
        if (tid < s) red[tid] += red[tid + s];
        __syncthreads();
    }
    if (tid == 0) g_Z[bh] = red[0];
}

// -------- out[j,d] = (rc/Z) * sum_i P[i,j] * V[i,d]  (A^T @ V) --------
__global__ void __launch_bounds__(256) av_k(
    const float* __restrict__ P, const float* __restrict__ V, float* __restrict__ O)
{
    __shared__ float Ps[64][65];   // [i][j]
    __shared__ float Vs[64][65];   // [i][d]
    const int bh = blockIdx.y, b = bh >> 3, h = bh & 7;
    const int j0 = blockIdx.x << 6;
    const int tid = threadIdx.x;
    const int r = tid >> 4, c4 = tid & 15;
    const int ty = tid >> 4, tx = tid & 15;
    float acc[4][4] = {};
    for (int i0 = 0; i0 < SEQ; i0 += 64) {
        __syncthreads();
        #pragma unroll
        for (int rr = 0; rr < 4; rr++) {
            int row = r + rr * 16;
            float4 pv = *(const float4*)(P + ((size_t)bh << 20) + (size_t)(i0 + row) * SEQ + j0 + c4*4);
            float4 vv = *(const float4*)(V + (size_t)(b*SEQ + i0 + row) * DMODEL + h*DEPTH + c4*4);
            Ps[row][c4*4+0] = pv.x; Ps[row][c4*4+1] = pv.y;
            Ps[row][c4*4+2] = pv.z; Ps[row][c4*4+3] = pv.w;
            Vs[row][c4*4+0] = vv.x; Vs[row][c4*4+1] = vv.y;
            Vs[row][c4*4+2] = vv.z; Vs[row][c4*4+3] = vv.w;
        }
        __syncthreads();
        #pragma unroll
        for (int i = 0; i < 64; i++) {
            float a[4], bb[4];
            #pragma unroll
            for (int jj = 0; jj < 4; jj++) a[jj] = Ps[i][ty*4 + jj];
            #pragma unroll
            for (int dd = 0; dd < 4; dd++) bb[dd] = Vs[i][tx*4 + dd];
            #pragma unroll
            for (int jj = 0; jj < 4; jj++)
                #pragma unroll
                for (int dd = 0; dd < 4; dd++)
                    acc[jj][dd] = fmaf(a[jj], bb[dd], acc[jj][dd]);
        }
    }
    const float scale = g_rc / g_Z[bh];
    #pragma unroll
    for (int jj = 0; jj < 4; jj++) {
        int j = j0 + ty*4 + jj;
        #pragma unroll
        for (int dd = 0; dd < 4; dd++) {
            int d = tx*4 + dd;
            O[(size_t)(b*SEQ + j) * DMODEL + h*DEPTH + d] = acc[jj][dd] * scale;
        }
    }
}

// -------- LayerNorm (one row per block, 256 threads, 2 elems each) --------
__global__ void ln_k(const float* __restrict__ X, const float* __restrict__ g,
                     const float* __restrict__ b, float* __restrict__ Y)
{
    __shared__ float red[256];
    const int row = blockIdx.x, tid = threadIdx.x;
    const float x0 = X[(size_t)row * DMODEL + tid];
    const float x1 = X[(size_t)row * DMODEL + 256 + tid];
    red[tid] = x0 + x1; __syncthreads();
    for (int s = 128; s > 0; s >>= 1) {
        if (tid < s) red[tid] += red[tid + s];
        __syncthreads();
    }
    const float mean = red[0] * (1.0f / DMODEL);
    __syncthreads();
    const float d0 = x0 - mean, d1 = x1 - mean;
    red[tid] = d0*d0 + d1*d1; __syncthreads();
    for (int s = 128; s > 0; s >>= 1) {
        if (tid < s) red[tid] += red[tid + s];
        __syncthreads();
    }
    const float rstd = rsqrtf(red[0] * (1.0f / DMODEL) + 1e-9f);
    Y[(size_t)row * DMODEL + tid]       = g[tid] * d0 * rstd + b[tid];
    Y[(size_t)row * DMODEL + 256 + tid] = g[tid + 256] * d1 * rstd + b[tid + 256];
}

// -------- final aw writeout: aw = P * rc / Z --------
__global__ void aw_k(const float* __restrict__ P, float* __restrict__ out) {
    const int idx = blockIdx.x * 256 + threadIdx.x;   // float4 index
    const int bh = idx >> 18;                          // (idx*4) >> 20
    const float s = g_rc / g_Z[bh];
    float4 v = ((const float4*)P)[idx];
    v.x *= s; v.y *= s; v.z *= s; v.w *= s;
    ((float4*)out)[idx] = v;
}

extern "C" void kernel_launch(void* const* d_in, const int* in_sizes, int n_in,
                              void* d_out, int out_size)
{
    const float* x_in  = (const float*)d_in[0];
    const float* mask  = (const float*)d_in[1];
    const int*   protok= (const int*)  d_in[2];
    const float* wq_w  = (const float*)d_in[3];
    const float* wq_b  = (const float*)d_in[4];
    const float* wk_w  = (const float*)d_in[5];
    const float* wk_b  = (const float*)d_in[6];
    const float* wv_w  = (const float*)d_in[7];
    const float* wv_b  = (const float*)d_in[8];
    const float* wo_w  = (const float*)d_in[9];
    const float* wo_b  = (const float*)d_in[10];
    const float* w1    = (const float*)d_in[11];
    const float* b1    = (const float*)d_in[12];
    const float* w2    = (const float*)d_in[13];
    const float* b2    = (const float*)d_in[14];
    const float* ln1g  = (const float*)d_in[15];
    const float* ln1b  = (const float*)d_in[16];
    const float* ln2g  = (const float*)d_in[17];
    const float* ln2b  = (const float*)d_in[18];
    float* out = (float*)d_out;

    float *q, *k, *v, *ao, *res, *o1, *xb, *hb, *L;
    cudaGetSymbolAddress((void**)&q,  g_q);
    cudaGetSymbolAddress((void**)&k,  g_k);
    cudaGetSymbolAddress((void**)&v,  g_v);
    cudaGetSymbolAddress((void**)&ao, g_ao);
    cudaGetSymbolAddress((void**)&res,g_res);
    cudaGetSymbolAddress((void**)&o1, g_o1);
    cudaGetSymbolAddress((void**)&xb, g_x);
    cudaGetSymbolAddress((void**)&hb, g_h);
    cudaGetSymbolAddress((void**)&L,  g_L);

    rc_k<<<1, 1024>>>(protok);

    const dim3 gNarrow(8, 32);    // N=512 GEMMs
    const dim3 gWide(32, 32);     // N=2048 GEMM
    for (int l = 0; l < NLAYERS; l++) {
        const float* xin = l ? xb : x_in;
        gemm_k<false, false><<<gNarrow, 256>>>(xin, wq_w, wq_b, nullptr, q, ROWS, DMODEL, DMODEL);
        gemm_k<false, false><<<gNarrow, 256>>>(xin, wk_w, wk_b, nullptr, k, ROWS, DMODEL, DMODEL);
        gemm_k<false, false><<<gNarrow, 256>>>(xin, wv_w, wv_b, nullptr, v, ROWS, DMODEL, DMODEL);
        qk_k<<<dim3(16, 16, 32), 256>>>(q, k, mask, L);
        max_k<<<dim3(64, 32), 256>>>(L);
        cmax_k<<<32, 64>>>();
        sexp_k<<<dim3(64, 32), 256>>>(L);
        csum_k<<<32, 64>>>();
        av_k<<<dim3(16, 32), 256>>>(L, v, ao);
        gemm_k<false, true><<<gNarrow, 256>>>(ao, wo_w, wo_b, xin, res, ROWS, DMODEL, DMODEL);
        ln_k<<<ROWS, 256>>>(res, ln1g, ln1b, o1);
        gemm_k<true, false><<<gWide, 256>>>(o1, w1, b1, nullptr, hb, ROWS, DFF, DMODEL);
        gemm_k<false, true><<<gNarrow, 256>>>(hb, w2, b2, o1, res, ROWS, DMODEL, DFF);
        float* xo = (l == NLAYERS - 1) ? out : xb;
        ln_k<<<ROWS, 256>>>(res, ln2g, ln2b, xo);
    }
    // aw of the last layer: P (in g_L) scaled by rc/Z
    aw_k<<<(int)(LSIZE / 4 / 256), 256>>>(L, out + XSIZE);
}

// round 2
// speedup vs baseline: 1.7622x; 1.7622x over previous
#include <cuda_runtime.h>
#include <cuda_bf16.h>
#include <cstddef>

// Problem constants
#define BATCH 4
#define SEQ   1024
#define DMODEL 512
#define HEADS 8
#define DEPTH 64
#define DFF   2048
#define NLAYERS 4
#define ROWS  (BATCH*SEQ)          // 4096
#define BH    (BATCH*HEADS)        // 32
#define LSIZE ((size_t)BH*SEQ*SEQ) // 33554432
#define XSIZE (ROWS*DMODEL)        // 2097152

// -------- scratch (device globals; no allocations) --------
__device__ float g_q[XSIZE];
__device__ float g_k[XSIZE];
__device__ float g_v[XSIZE];
__device__ float g_ao[XSIZE];
__device__ float g_res[XSIZE];
__device__ float g_o1[XSIZE];
__device__ float g_x[XSIZE];
__device__ float g_h[ROWS*DFF];
__device__ float g_L[LSIZE];
__device__ float g_ps[BH*64];
__device__ float g_Z[BH];
__device__ unsigned g_Mu[BH];
__device__ float g_rc;

// -------- helpers --------
__device__ __forceinline__ unsigned f2tf(float f) {
    unsigned r; asm("cvt.rna.tf32.f32 %0, %1;" : "=r"(r) : "f"(f)); return r;
}
__device__ __forceinline__ void mma8(float* c, const unsigned* a, const unsigned* b) {
    asm volatile("mma.sync.aligned.m16n8k8.row.col.f32.tf32.tf32.f32 "
        "{%0,%1,%2,%3}, {%4,%5,%6,%7}, {%8,%9}, {%0,%1,%2,%3};\n"
        : "+f"(c[0]), "+f"(c[1]), "+f"(c[2]), "+f"(c[3])
        : "r"(a[0]), "r"(a[1]), "r"(a[2]), "r"(a[3]), "r"(b[0]), "r"(b[1]));
}
// order-preserving float<->uint for atomicMax
__device__ __forceinline__ unsigned fenc(float f) {
    unsigned u = __float_as_uint(f);
    return (u & 0x80000000u) ? ~u : (u | 0x80000000u);
}
__device__ __forceinline__ float fdec(unsigned u) {
    return (u & 0x80000000u) ? __uint_as_float(u & 0x7fffffffu) : __uint_as_float(~u);
}
// fast exp on FMA pipe
__device__ __forceinline__ float fexp(float x) {
    float t = x * 1.44269504089f;
    t = fmaxf(t, -126.0f);
    float fi = floorf(t);
    float f  = t - fi;
    float p = 1.54035304e-4f;
    p = fmaf(p, f, 1.33335581e-3f);
    p = fmaf(p, f, 9.61812911e-3f);
    p = fmaf(p, f, 5.55041087e-2f);
    p = fmaf(p, f, 2.40226507e-1f);
    p = fmaf(p, f, 6.93147181e-1f);
    p = fmaf(p, f, 1.0f);
    int ei = (int)fi;
    return __int_as_float((ei + 127) << 23) * p;
}

// -------- row count + per-replay init --------
__global__ void rc_k(const int* __restrict__ pk) {
    __shared__ int red[1024];
    int tid = threadIdx.x;
    red[tid] = (pk[tid] != 0) ? 1 : 0;
    __syncthreads();
    for (int s = 512; s > 0; s >>= 1) {
        if (tid < s) red[tid] += red[tid + s];
        __syncthreads();
    }
    if (tid == 0) g_rc = (float)red[0];
    if (tid < BH) g_Mu[tid] = 0u;
}

// ============================================================
// TF32 MMA GEMM: C[M,N] = A[M,K] @ B[K,N] + bias (+Res) (relu)
// BM=128 BN=128 BK=8, 256 thr (8 warps, 2x4), warp tile 64x32
// ============================================================
template<bool RELU, bool RES>
__global__ void __launch_bounds__(256, 2) gemm_mma(
    const float* __restrict__ A, const float* __restrict__ Bw,
    const float* __restrict__ bias, const float* __restrict__ Rs,
    float* __restrict__ C, int M, int N, int K)
{
    __shared__ unsigned As[2][8][132];
    __shared__ unsigned Bs[2][8][132];
    const int tid = threadIdx.x;
    const int m0 = blockIdx.y << 7, n0 = blockIdx.x << 7;
    const int wid = tid >> 5, lane = tid & 31;
    const int grp = lane >> 2, tig = lane & 3;
    const int wm = (wid >> 2) << 6;
    const int wn = (wid & 3) << 5;
    const int am = tid >> 1, ak = (tid & 1) << 2;
    const int bk = tid >> 5, bn = (tid & 31) << 2;

    float4 ra = *(const float4*)(A + (size_t)(m0 + am) * K + ak);
    float4 rb = *(const float4*)(Bw + (size_t)bk * N + n0 + bn);
    As[0][ak+0][am] = f2tf(ra.x); As[0][ak+1][am] = f2tf(ra.y);
    As[0][ak+2][am] = f2tf(ra.z); As[0][ak+3][am] = f2tf(ra.w);
    *(uint4*)&Bs[0][bk][bn] = make_uint4(f2tf(rb.x), f2tf(rb.y), f2tf(rb.z), f2tf(rb.w));
    __syncthreads();

    float acc[4][4][4] = {};
    const int KT = K >> 3;
    for (int it = 0; it < KT; ++it) {
        const int cur = it & 1;
        if (it + 1 < KT) {
            const int k0 = (it + 1) << 3;
            ra = *(const float4*)(A + (size_t)(m0 + am) * K + k0 + ak);
            rb = *(const float4*)(Bw + (size_t)(k0 + bk) * N + n0 + bn);
        }
        unsigned af[4][4], bf[4][2];
        #pragma unroll
        for (int mt = 0; mt < 4; mt++) {
            const int mb = wm + mt*16 + grp;
            af[mt][0] = As[cur][tig  ][mb];
            af[mt][1] = As[cur][tig  ][mb+8];
            af[mt][2] = As[cur][tig+4][mb];
            af[mt][3] = As[cur][tig+4][mb+8];
        }
        #pragma unroll
        for (int nt = 0; nt < 4; nt++) {
            const int nb = wn + nt*8 + grp;
            bf[nt][0] = Bs[cur][tig  ][nb];
            bf[nt][1] = Bs[cur][tig+4][nb];
        }
        #pragma unroll
        for (int mt = 0; mt < 4; mt++)
            #pragma unroll
            for (int nt = 0; nt < 4; nt++)
                mma8(acc[mt][nt], af[mt], bf[nt]);
        if (it + 1 < KT) {
            const int nxt = cur ^ 1;
            As[nxt][ak+0][am] = f2tf(ra.x); As[nxt][ak+1][am] = f2tf(ra.y);
            As[nxt][ak+2][am] = f2tf(ra.z); As[nxt][ak+3][am] = f2tf(ra.w);
            *(uint4*)&Bs[nxt][bk][bn] = make_uint4(f2tf(rb.x), f2tf(rb.y), f2tf(rb.z), f2tf(rb.w));
        }
        __syncthreads();
    }
    #pragma unroll
    for (int mt = 0; mt < 4; mt++) {
        #pragma unroll
        for (int nt = 0; nt < 4; nt++) {
            const int n = n0 + wn + nt*8 + tig*2;
            const float b0v = bias[n], b1v = bias[n+1];
            #pragma unroll
            for (int half = 0; half < 2; half++) {
                const int m = m0 + wm + mt*16 + grp + half*8;
                float v0 = acc[mt][nt][half*2+0] + b0v;
                float v1 = acc[mt][nt][half*2+1] + b1v;
                if (RES) {
                    v0 += Rs[(size_t)m*N + n];
                    v1 += Rs[(size_t)m*N + n + 1];
                }
                if (RELU) { v0 = fmaxf(v0, 0.0f); v1 = fmaxf(v1, 0.0f); }
                *(float2*)(C + (size_t)m*N + n) = make_float2(v0, v1);
            }
        }
    }
}

// ============================================================
// QK^T + mask + scale -> L, fused global-max atomic (per bh)
// M=N=1024, K=64. BM=BN=128, BK=8
// ============================================================
__global__ void __launch_bounds__(256, 2) qk_mma(
    const float* __restrict__ Q, const float* __restrict__ Kg,
    const float* __restrict__ mask, float* __restrict__ L)
{
    __shared__ unsigned As[2][8][132];
    __shared__ unsigned Bs[2][8][132];
    const int tid = threadIdx.x;
    const int bh = blockIdx.z, b = bh >> 3, h = bh & 7;
    const int i0 = blockIdx.y << 7, j0 = blockIdx.x << 7;
    const int wid = tid >> 5, lane = tid & 31;
    const int grp = lane >> 2, tig = lane & 3;
    const int wm = (wid >> 2) << 6;
    const int wn = (wid & 3) << 5;
    const int am = tid >> 1, ak = (tid & 1) << 2;
    const float* Qb = Q + (size_t)(b*SEQ + i0) * DMODEL + h*DEPTH;
    const float* Kb = Kg + (size_t)(b*SEQ + j0) * DMODEL + h*DEPTH;

    float4 ra = *(const float4*)(Qb + (size_t)am * DMODEL + ak);
    float4 rb = *(const float4*)(Kb + (size_t)am * DMODEL + ak);
    As[0][ak+0][am] = f2tf(ra.x); As[0][ak+1][am] = f2tf(ra.y);
    As[0][ak+2][am] = f2tf(ra.z); As[0][ak+3][am] = f2tf(ra.w);
    Bs[0][ak+0][am] = f2tf(rb.x); Bs[0][ak+1][am] = f2tf(rb.y);
    Bs[0][ak+2][am] = f2tf(rb.z); Bs[0][ak+3][am] = f2tf(rb.w);
    __syncthreads();

    float acc[4][4][4] = {};
    const int KT = DEPTH >> 3;   // 8
    for (int it = 0; it < KT; ++it) {
        const int cur = it & 1;
        if (it + 1 < KT) {
            const int k0 = (it + 1) << 3;
            ra = *(const float4*)(Qb + (size_t)am * DMODEL + k0 + ak);
            rb = *(const float4*)(Kb + (size_t)am * DMODEL + k0 + ak);
        }
        unsigned af[4][4], bf[4][2];
        #pragma unroll
        for (int mt = 0; mt < 4; mt++) {
            const int mb = wm + mt*16 + grp;
            af[mt][0] = As[cur][tig  ][mb];
            af[mt][1] = As[cur][tig  ][mb+8];
            af[mt][2] = As[cur][tig+4][mb];
            af[mt][3] = As[cur][tig+4][mb+8];
        }
        #pragma unroll
        for (int nt = 0; nt < 4; nt++) {
            const int nb = wn + nt*8 + grp;
            bf[nt][0] = Bs[cur][tig  ][nb];
            bf[nt][1] = Bs[cur][tig+4][nb];
        }
        #pragma unroll
        for (int mt = 0; mt < 4; mt++)
            #pragma unroll
            for (int nt = 0; nt < 4; nt++)
                mma8(acc[mt][nt], af[mt], bf[nt]);
        if (it + 1 < KT) {
            const int nxt = cur ^ 1;
            As[nxt][ak+0][am] = f2tf(ra.x); As[nxt][ak+1][am] = f2tf(ra.y);
            As[nxt][ak+2][am] = f2tf(ra.z); As[nxt][ak+3][am] = f2tf(ra.w);
            Bs[nxt][ak+0][am] = f2tf(rb.x); Bs[nxt][ak+1][am] = f2tf(rb.y);
            Bs[nxt][ak+2][am] = f2tf(rb.z); Bs[nxt][ak+3][am] = f2tf(rb.w);
        }
        __syncthreads();
    }

    float lmax = -3.4e38f;
    float* Lb = L + ((size_t)bh << 20);
    #pragma unroll
    for (int mt = 0; mt < 4; mt++) {
        #pragma unroll
        for (int nt = 0; nt < 4; nt++) {
            const int gj = j0 + wn + nt*8 + tig*2;
            #pragma unroll
            for (int half = 0; half < 2; half++) {
                const int gi = i0 + wm + mt*16 + grp + half*8;
                const float* mrow = mask + (size_t)(b*SEQ + gi) * SEQ;
                float v0 = (acc[mt][nt][half*2+0] - 1e9f * mrow[gj])   * 0.125f;
                float v1 = (acc[mt][nt][half*2+1] - 1e9f * mrow[gj+1]) * 0.125f;
                *(float2*)(Lb + (size_t)gi * SEQ + gj) = make_float2(v0, v1);
                lmax = fmaxf(lmax, fmaxf(v0, v1));
            }
        }
    }
    #pragma unroll
    for (int o = 16; o; o >>= 1)
        lmax = fmaxf(lmax, __shfl_xor_sync(0xffffffffu, lmax, o));
    __shared__ float wred[8];
    if (lane == 0) wred[wid] = lmax;
    __syncthreads();
    if (tid == 0) {
        float m = wred[0];
        #pragma unroll
        for (int i = 1; i < 8; i++) m = fmaxf(m, wred[i]);
        atomicMax(&g_Mu[bh], fenc(m));
    }
}

// -------- P = exp(L - M) overwrite + partial sums --------
__global__ void sexp_k(float* __restrict__ L) {
    const int bh = blockIdx.y, blk = blockIdx.x, tid = threadIdx.x;
    const float M = fdec(g_Mu[bh]);
    float4* p = (float4*)(L + ((size_t)bh << 20) + (size_t)blk * 16384);
    float s = 0.0f;
    #pragma unroll
    for (int it = 0; it < 16; it++) {
        float4 v = p[tid + it * 256];
        v.x = fexp(v.x - M); v.y = fexp(v.y - M);
        v.z = fexp(v.z - M); v.w = fexp(v.w - M);
        p[tid + it * 256] = v;
        s += (v.x + v.y) + (v.z + v.w);
    }
    __shared__ float red[256];
    red[tid] = s; __syncthreads();
    for (int st = 128; st > 0; st >>= 1) {
        if (tid < st) red[tid] += red[tid + st];
        __syncthreads();
    }
    if (tid == 0) g_ps[bh * 64 + blk] = red[0];
}

__global__ void csum_k() {
    const int bh = blockIdx.x, tid = threadIdx.x;
    __shared__ float red[64];
    red[tid] = g_ps[bh * 64 + tid]; __syncthreads();
    for (int s = 32; s > 0; s >>= 1) {
        if (tid < s) red[tid] += red[tid + s];
        __syncthreads();
    }
    if (tid == 0) { g_Z[bh] = red[0]; g_Mu[bh] = 0u; }  // reset max for next layer
}

// ============================================================
// out[j,d] = (rc/Z) * sum_i P[i,j] V[i,d]   (A^T @ V), per bh
// BM=128 (j), BN=64 (d), BK=16, warp tile 64x16 (2x4 warps)
// ============================================================
__global__ void __launch_bounds__(256, 2) av_mma(
    const float* __restrict__ P, const float* __restrict__ V, float* __restrict__ O)
{
    __shared__ unsigned Ps[2][16][132];
    __shared__ unsigned Vs[2][16][68];
    const int tid = threadIdx.x;
    const int bh = blockIdx.y, b = bh >> 3, h = bh & 7;
    const int j0 = blockIdx.x << 7;
    const int wid = tid >> 5, lane = tid & 31;
    const int grp = lane >> 2, tig = lane & 3;
    const int wm = (wid >> 2) << 6;     // 0,64
    const int wn = (wid & 3) << 4;      // 0,16,32,48
    const int pi = tid >> 5, pj = (tid & 31) << 2;
    const int vi = tid >> 4, vd = (tid & 15) << 2;
    const float* Pb = P + ((size_t)bh << 20) + j0;
    const float* Vb = V + (size_t)(b*SEQ) * DMODEL + h*DEPTH;

    float4 rp0 = *(const float4*)(Pb + (size_t)pi * SEQ + pj);
    float4 rp1 = *(const float4*)(Pb + (size_t)(pi + 8) * SEQ + pj);
    float4 rv  = *(const float4*)(Vb + (size_t)vi * DMODEL + vd);
    *(uint4*)&Ps[0][pi  ][pj] = make_uint4(f2tf(rp0.x), f2tf(rp0.y), f2tf(rp0.z), f2tf(rp0.w));
    *(uint4*)&Ps[0][pi+8][pj] = make_uint4(f2tf(rp1.x), f2tf(rp1.y), f2tf(rp1.z), f2tf(rp1.w));
    *(uint4*)&Vs[0][vi][vd]   = make_uint4(f2tf(rv.x),  f2tf(rv.y),  f2tf(rv.z),  f2tf(rv.w));
    __syncthreads();

    float acc[4][2][4] = {};
    const int KT = SEQ >> 4;   // 64
    for (int it = 0; it < KT; ++it) {
        const int cur = it & 1;
        if (it + 1 < KT) {
            const int i0n = (it + 1) << 4;
            rp0 = *(const float4*)(Pb + (size_t)(i0n + pi) * SEQ + pj);
            rp1 = *(const float4*)(Pb + (size_t)(i0n + pi + 8) * SEQ + pj);
            rv  = *(const float4*)(Vb + (size_t)(i0n + vi) * DMODEL + vd);
        }
        #pragma unroll
        for (int ks = 0; ks < 16; ks += 8) {
            unsigned af[4][4], bf[2][2];
            #pragma unroll
            for (int mt = 0; mt < 4; mt++) {
                const int mb = wm + mt*16 + grp;
                af[mt][0] = Ps[cur][ks+tig  ][mb];
                af[mt][1] = Ps[cur][ks+tig  ][mb+8];
                af[mt][2] = Ps[cur][ks+tig+4][mb];
                af[mt][3] = Ps[cur][ks+tig+4][mb+8];
            }
            #pragma unroll
            for (int nt = 0; nt < 2; nt++) {
                const int nb = wn + nt*8 + grp;
                bf[nt][0] = Vs[cur][ks+tig  ][nb];
                bf[nt][1] = Vs[cur][ks+tig+4][nb];
            }
            #pragma unroll
            for (int mt = 0; mt < 4; mt++)
                #pragma unroll
                for (int nt = 0; nt < 2; nt++)
                    mma8(acc[mt][nt], af[mt], bf[nt]);
        }
        if (it + 1 < KT) {
            const int nxt = cur ^ 1;
            *(uint4*)&Ps[nxt][pi  ][pj] = make_uint4(f2tf(rp0.x), f2tf(rp0.y), f2tf(rp0.z), f2tf(rp0.w));
            *(uint4*)&Ps[nxt][pi+8][pj] = make_uint4(f2tf(rp1.x), f2tf(rp1.y), f2tf(rp1.z), f2tf(rp1.w));
            *(uint4*)&Vs[nxt][vi][vd]   = make_uint4(f2tf(rv.x),  f2tf(rv.y),  f2tf(rv.z),  f2tf(rv.w));
        }
        __syncthreads();
    }
    const float scale = g_rc / g_Z[bh];
    #pragma unroll
    for (int mt = 0; mt < 4; mt++) {
        #pragma unroll
        for (int nt = 0; nt < 2; nt++) {
            const int d = wn + nt*8 + tig*2;
            #pragma unroll
            for (int half = 0; half < 2; half++) {
                const int gj = j0 + wm + mt*16 + grp + half*8;
                float v0 = acc[mt][nt][half*2+0] * scale;
                float v1 = acc[mt][nt][half*2+1] * scale;
                *(float2*)(O + (size_t)(b*SEQ + gj) * DMODEL + h*DEPTH + d) = make_float2(v0, v1);
            }
        }
    }
}

// -------- LayerNorm --------
__global__ void ln_k(const float* __restrict__ X, const float* __restrict__ g,
                     const float* __restrict__ b, float* __restrict__ Y)
{
    __shared__ float red[256];
    const int row = blockIdx.x, tid = threadIdx.x;
    const float x0 = X[(size_t)row * DMODEL + tid];
    const float x1 = X[(size_t)row * DMODEL + 256 + tid];
    red[tid] = x0 + x1; __syncthreads();
    for (int s = 128; s > 0; s >>= 1) {
        if (tid < s) red[tid] += red[tid + s];
        __syncthreads();
    }
    const float mean = red[0] * (1.0f / DMODEL);
    __syncthreads();
    const float d0 = x0 - mean, d1 = x1 - mean;
    red[tid] = d0*d0 + d1*d1; __syncthreads();
    for (int s = 128; s > 0; s >>= 1) {
        if (tid < s) red[tid] += red[tid + s];
        __syncthreads();
    }
    const float rstd = rsqrtf(red[0] * (1.0f / DMODEL) + 1e-9f);
    Y[(size_t)row * DMODEL + tid]       = g[tid] * d0 * rstd + b[tid];
    Y[(size_t)row * DMODEL + 256 + tid] = g[tid + 256] * d1 * rstd + b[tid + 256];
}

// -------- final aw writeout: aw = P * rc / Z --------
__global__ void aw_k(const float* __restrict__ P, float* __restrict__ out) {
    const int idx = blockIdx.x * 256 + threadIdx.x;
    const int bh = idx >> 18;
    const float s = g_rc / g_Z[bh];
    float4 v = ((const float4*)P)[idx];
    v.x *= s; v.y *= s; v.z *= s; v.w *= s;
    ((float4*)out)[idx] = v;
}

extern "C" void kernel_launch(void* const* d_in, const int* in_sizes, int n_in,
                              void* d_out, int out_size)
{
    const float* x_in  = (const float*)d_in[0];
    const float* mask  = (const float*)d_in[1];
    const int*   protok= (const int*)  d_in[2];
    const float* wq_w  = (const float*)d_in[3];
    const float* wq_b  = (const float*)d_in[4];
    const float* wk_w  = (const float*)d_in[5];
    const float* wk_b  = (const float*)d_in[6];
    const float* wv_w  = (const float*)d_in[7];
    const float* wv_b  = (const float*)d_in[8];
    const float* wo_w  = (const float*)d_in[9];
    const float* wo_b  = (const float*)d_in[10];
    const float* w1    = (const float*)d_in[11];
    const float* b1    = (const float*)d_in[12];
    const float* w2    = (const float*)d_in[13];
    const float* b2    = (const float*)d_in[14];
    const float* ln1g  = (const float*)d_in[15];
    const float* ln1b  = (const float*)d_in[16];
    const float* ln2g  = (const float*)d_in[17];
    const float* ln2b  = (const float*)d_in[18];
    float* out = (float*)d_out;

    float *q, *k, *v, *ao, *res, *o1, *xb, *hb, *L;
    cudaGetSymbolAddress((void**)&q,  g_q);
    cudaGetSymbolAddress((void**)&k,  g_k);
    cudaGetSymbolAddress((void**)&v,  g_v);
    cudaGetSymbolAddress((void**)&ao, g_ao);
    cudaGetSymbolAddress((void**)&res,g_res);
    cudaGetSymbolAddress((void**)&o1, g_o1);
    cudaGetSymbolAddress((void**)&xb, g_x);
    cudaGetSymbolAddress((void**)&hb, g_h);
    cudaGetSymbolAddress((void**)&L,  g_L);

    rc_k<<<1, 1024>>>(protok);

    const dim3 gN512(4, 32);     // N=512 GEMMs (BN=128)
    const dim3 gN2048(16, 32);   // N=2048 GEMM
    for (int l = 0; l < NLAYERS; l++) {
        const float* xin = l ? xb : x_in;
        gemm_mma<false, false><<<gN512, 256>>>(xin, wq_w, wq_b, nullptr, q, ROWS, DMODEL, DMODEL);
        gemm_mma<false, false><<<gN512, 256>>>(xin, wk_w, wk_b, nullptr, k, ROWS, DMODEL, DMODEL);
        gemm_mma<false, false><<<gN512, 256>>>(xin, wv_w, wv_b, nullptr, v, ROWS, DMODEL, DMODEL);
        qk_mma<<<dim3(8, 8, 32), 256>>>(q, k, mask, L);
        sexp_k<<<dim3(64, 32), 256>>>(L);
        csum_k<<<32, 64>>>();
        av_mma<<<dim3(8, 32), 256>>>(L, v, ao);
        gemm_mma<false, true><<<gN512, 256>>>(ao, wo_w, wo_b, xin, res, ROWS, DMODEL, DMODEL);
        ln_k<<<ROWS, 256>>>(res, ln1g, ln1b, o1);
        gemm_mma<true, false><<<gN2048, 256>>>(o1, w1, b1, nullptr, hb, ROWS, DFF, DMODEL);
        gemm_mma<false, true><<<gN512, 256>>>(hb, w2, b2, o1, res, ROWS, DMODEL, DFF);
        float* xo = (l == NLAYERS - 1) ? out : xb;
        ln_k<<<ROWS, 256>>>(res, ln2g, ln2b, xo);
    }
    aw_k<<<(int)(LSIZE / 4 / 256), 256>>>(L, out + XSIZE);
}